// round 1
// baseline (speedup 1.0000x reference)
#include <cuda_runtime.h>
#include <cuda_bf16.h>

#define NB 8
#define NPTS 16384
#define NQ 1024
#define NC 64
#define NS 32
#define R2 0.04f
#define WPB 8   // warps per block

__global__ __launch_bounds__(WPB * 32) void qag_kernel(
    const float* __restrict__ xyz,      // (B, N, 3)
    const float* __restrict__ new_xyz,  // (B, S, 3)
    const float* __restrict__ feats,    // (B, C, N)
    float* __restrict__ out)            // (B, 3+C, S, NS)
{
    const int lane = threadIdx.x & 31;
    const int wid  = threadIdx.x >> 5;
    const int q = blockIdx.x * WPB + wid;      // global query id in [0, B*S)
    if (q >= NB * NQ) return;
    const int b = q / NQ;
    const int s = q % NQ;

    __shared__ int idx_buf_all[WPB][NS];
    int* idx_buf = idx_buf_all[wid];

    const float qx = new_xyz[q * 3 + 0];
    const float qy = new_xyz[q * 3 + 1];
    const float qz = new_xyz[q * 3 + 2];

    const float* xb = xyz + (size_t)b * NPTS * 3;

    // ---- ball query: sequential scan with early exit ----
    int cnt = 0;
    for (int j0 = 0; j0 < NPTS; j0 += 32) {
        const int j = j0 + lane;
        const float dx = xb[j * 3 + 0] - qx;
        const float dy = xb[j * 3 + 1] - qy;
        const float dz = xb[j * 3 + 2] - qz;
        const float d2 = dx * dx + dy * dy + dz * dz;
        const bool within = d2 < R2;
        const unsigned mask = __ballot_sync(0xFFFFFFFFu, within);
        if (within) {
            const int pos = cnt + __popc(mask & ((1u << lane) - 1u));
            if (pos < NS) idx_buf[pos] = j;
        }
        cnt += __popc(mask);
        if (cnt >= NS) break;   // uniform across warp
    }
    __syncwarp();
    const int eff = cnt < NS ? cnt : NS;
    int first = 0;
    if (eff > 0) first = idx_buf[0];
    __syncwarp();
    if (lane >= eff) idx_buf[lane] = first;   // pad with first valid (0 if none)
    __syncwarp();
    const int my = idx_buf[lane];             // lane k owns sample k

    // ---- grouped xyz (channels 0..2), coalesced writes ----
    const float px = xb[my * 3 + 0] - qx;
    const float py = xb[my * 3 + 1] - qy;
    const float pz = xb[my * 3 + 2] - qz;

    const size_t CH = (size_t)NQ * NS;                         // channel stride
    float* ob = out + ((size_t)b * (3 + NC) * NQ + s) * NS + lane;
    ob[0 * CH] = px;
    ob[1 * CH] = py;
    ob[2 * CH] = pz;

    // ---- grouped features (channels 3..66) ----
    const float* fb = feats + (size_t)b * NC * NPTS + my;
    float* of = ob + 3 * CH;
    #pragma unroll 8
    for (int c = 0; c < NC; ++c) {
        of[c * CH] = __ldg(fb + (size_t)c * NPTS);
    }
}

extern "C" void kernel_launch(void* const* d_in, const int* in_sizes, int n_in,
                              void* d_out, int out_size) {
    const float* xyz     = (const float*)d_in[0];
    const float* new_xyz = (const float*)d_in[1];
    const float* feats   = (const float*)d_in[2];
    float* out = (float*)d_out;

    const int nq = NB * NQ;                 // 8192 queries, one warp each
    const int blocks = (nq + WPB - 1) / WPB;
    qag_kernel<<<blocks, WPB * 32>>>(xyz, new_xyz, feats, out);
}